// round 13
// baseline (speedup 1.0000x reference)
#include <cuda_runtime.h>
#include <cuda_bf16.h>
#include <cstdint>

#define NB   4
#define CIN  512
#define HWD  16384
#define KCL  19
#define KC   256
#define OUTC 512

#define BM 128
#define BN 128
#define BK 32

typedef unsigned long long u64;
typedef unsigned int u32;

// ---------------- packed f32x2 helpers ----------------
__device__ __forceinline__ u64 pk2(float lo, float hi) {
    u64 r; asm("mov.b64 %0, {%1, %2};" : "=l"(r) : "f"(lo), "f"(hi)); return r;
}
__device__ __forceinline__ void ffma2(u64& d, u64 a, u64 b) {
    asm("fma.rn.f32x2 %0, %1, %2, %0;" : "+l"(d) : "l"(a), "l"(b));
}
__device__ __forceinline__ void fadd2(u64& d, u64 a) {
    asm("add.rn.f32x2 %0, %0, %1;" : "+l"(d) : "l"(a));
}
__device__ __forceinline__ float2 upk(u64 v) {
    float2 f; asm("mov.b64 {%0, %1}, %2;" : "=f"(f.x), "=f"(f.y) : "l"(v)); return f;
}
__device__ __forceinline__ void split_bf16(float v, __nv_bfloat16& h, __nv_bfloat16& l) {
    h = __float2bfloat16(v);
    l = __float2bfloat16(v - __bfloat162float(h));
}
__device__ __forceinline__ u32 pack_bf2(__nv_bfloat16 a, __nv_bfloat16 b) {
    __nv_bfloat162 t; t.x = a; t.y = b;
    return *reinterpret_cast<u32*>(&t);
}

// ---------------- mma / async helpers ----------------
__device__ __forceinline__ u32 smem_u32(const void* p) {
    u32 a;
    asm("{ .reg .u64 t; cvta.to.shared.u64 t, %1; cvt.u32.u64 %0, t; }" : "=r"(a) : "l"(p));
    return a;
}
__device__ __forceinline__ void ldsm4(u32* r, u32 addr) {
    asm volatile("ldmatrix.sync.aligned.m8n8.x4.shared.b16 {%0,%1,%2,%3}, [%4];\n"
        : "=r"(r[0]), "=r"(r[1]), "=r"(r[2]), "=r"(r[3]) : "r"(addr));
}
__device__ __forceinline__ void ldsm4t(u32* r, u32 addr) {
    asm volatile("ldmatrix.sync.aligned.m8n8.x4.trans.shared.b16 {%0,%1,%2,%3}, [%4];\n"
        : "=r"(r[0]), "=r"(r[1]), "=r"(r[2]), "=r"(r[3]) : "r"(addr));
}
__device__ __forceinline__ void mma16816(float* d, const u32* a, const u32* b) {
    asm volatile(
        "mma.sync.aligned.m16n8k16.row.col.f32.bf16.bf16.f32 "
        "{%0,%1,%2,%3}, {%4,%5,%6,%7}, {%8,%9}, {%0,%1,%2,%3};\n"
        : "+f"(d[0]), "+f"(d[1]), "+f"(d[2]), "+f"(d[3])
        : "r"(a[0]), "r"(a[1]), "r"(a[2]), "r"(a[3]), "r"(b[0]), "r"(b[1]));
}
__device__ __forceinline__ void cp16(u32 dst, const void* src) {
    asm volatile("cp.async.cg.shared.global [%0], [%1], 16;" :: "r"(dst), "l"(src) : "memory");
}
#define CP_COMMIT() asm volatile("cp.async.commit_group;" ::: "memory")
#define CP_WAIT0()  asm volatile("cp.async.wait_group 0;" ::: "memory")

// ---------------- scratch (device globals, zero-initialized) ----------------
__device__ float g_p[NB * KCL * HWD];
__device__ float g_proxy[NB * CIN * 20];
__device__ float g_t1[NB * KC * 20];
__device__ float g_kk[NB * KC * 20];
__device__ float g_val[NB * KC * 20];
__device__ float g_wv[NB * OUTC * 20];
__device__ float g_q2[(size_t)NB * KC * HWD];

// split bf16 activation planes: [n][hi plane | lo plane]
__device__ __nv_bfloat16 g_feats2[(size_t)NB * 2 * CIN * HWD];
__device__ __nv_bfloat16 g_q12[(size_t)NB * 2 * KC * HWD];
__device__ __nv_bfloat16 g_up2[(size_t)NB * 2 * CIN * HWD];

// split weights: [hi M*K][lo M*K]
__device__ __nv_bfloat16 g_wp1_2[2 * (size_t)KC * CIN];
__device__ __nv_bfloat16 g_wp2_2[2 * (size_t)KC * KC];
__device__ __nv_bfloat16 g_wf_2[2 * (size_t)OUTC * 2 * CIN];

// ==================== spatial softmax per (n,k) ====================
__global__ __launch_bounds__(256) void softmax_k(const float* __restrict__ probs) {
    const int row = blockIdx.x;
    const float* x = probs + (size_t)row * HWD;
    float* y = g_p + (size_t)row * HWD;
    __shared__ float red[8];
    const int tid = threadIdx.x, lane = tid & 31, warp = tid >> 5;

    float m = -3.4e38f;
    for (int i = tid; i < HWD; i += 256) m = fmaxf(m, x[i]);
    #pragma unroll
    for (int s = 16; s; s >>= 1) m = fmaxf(m, __shfl_xor_sync(0xffffffffu, m, s));
    if (!lane) red[warp] = m;
    __syncthreads();
    m = red[0];
    #pragma unroll
    for (int w = 1; w < 8; w++) m = fmaxf(m, red[w]);

    float sum = 0.f;
    for (int i = tid; i < HWD; i += 256) sum += __expf(x[i] - m);
    #pragma unroll
    for (int s = 16; s; s >>= 1) sum += __shfl_xor_sync(0xffffffffu, sum, s);
    __syncthreads();
    if (!lane) red[warp] = sum;
    __syncthreads();
    sum = red[0];
    #pragma unroll
    for (int w = 1; w < 8; w++) sum += red[w];
    const float inv = 1.f / sum;

    for (int i = tid; i < HWD; i += 256) y[i] = __expf(x[i] - m) * inv;
}

// ==================== proxy[n,c,k] = sum_s p[n,k,s] feats[n,c,s] ====================
__global__ __launch_bounds__(256) void proxy_k(const float* __restrict__ feats) {
    const int n = blockIdx.y;
    const int warp = threadIdx.x >> 5, lane = threadIdx.x & 31;
    const int c0 = blockIdx.x * 16 + warp * 2;

    __shared__ __align__(16) float ps[128 * 22];

    u64 acc0[10], acc1[10];
    #pragma unroll
    for (int t = 0; t < 10; t++) { acc0[t] = 0ull; acc1[t] = 0ull; }

    const float* f0p = feats + ((size_t)(n * CIN + c0)) * HWD;
    const float* f1p = f0p + HWD;
    const float* pn  = g_p + (size_t)n * KCL * HWD;

    for (int sc = 0; sc < HWD; sc += 128) {
        __syncthreads();
        for (int idx = threadIdx.x; idx < KCL * 128; idx += 256) {
            int k = idx >> 7, j = idx & 127;
            ps[j * 22 + k] = pn[(size_t)k * HWD + sc + j];
        }
        if (threadIdx.x < 128) ps[threadIdx.x * 22 + 19] = 0.f;
        __syncthreads();

        #pragma unroll
        for (int jj = 0; jj < 4; jj++) {
            int j = lane + jj * 32;
            float f0 = f0p[sc + j];
            float f1 = f1p[sc + j];
            u64 f02 = pk2(f0, f0), f12 = pk2(f1, f1);
            const u64* pr = (const u64*)&ps[j * 22];
            #pragma unroll
            for (int t = 0; t < 10; t++) {
                u64 pv = pr[t];
                ffma2(acc0[t], f02, pv);
                ffma2(acc1[t], f12, pv);
            }
        }
    }
    #pragma unroll
    for (int t = 0; t < 10; t++) {
        #pragma unroll
        for (int s = 16; s; s >>= 1) {
            fadd2(acc0[t], __shfl_xor_sync(0xffffffffu, acc0[t], s));
            fadd2(acc1[t], __shfl_xor_sync(0xffffffffu, acc1[t], s));
        }
    }
    if (lane == 0) {
        float* o0 = g_proxy + (size_t)(n * CIN + c0) * 20;
        float* o1 = o0 + 20;
        #pragma unroll
        for (int t = 0; t < 10; t++) {
            float2 v0 = upk(acc0[t]);
            float2 v1 = upk(acc1[t]);
            o0[2 * t] = v0.x;
            o1[2 * t] = v1.x;
            if (2 * t + 1 < KCL) { o0[2 * t + 1] = v0.y; o1[2 * t + 1] = v1.y; }
        }
    }
}

// ==================== object micro GEMM (CBR epilogue) ====================
__global__ __launch_bounds__(256) void obj_gemm(
    const float* __restrict__ W, const float* __restrict__ bv,
    const float* __restrict__ sv, const float* __restrict__ tv,
    const float* __restrict__ src, float* __restrict__ dst, int Cin)
{
    extern __shared__ float src_s[];
    const int n = blockIdx.y;
    for (int idx = threadIdx.x; idx < Cin * 20; idx += 256)
        src_s[(idx / 20) * 22 + (idx % 20)] = src[(size_t)n * Cin * 20 + idx];
    __syncthreads();

    const int g  = threadIdx.x & 15;
    const int ol = threadIdx.x >> 4;
    const int o  = blockIdx.x * 16 + ol;

    u64 acc[10];
    #pragma unroll
    for (int t = 0; t < 10; t++) acc[t] = 0ull;

    const float* wrow = W + (size_t)o * Cin;
    const int ncc = Cin >> 4;
    for (int cc = 0; cc < ncc; cc++) {
        int c = g + cc * 16;
        float w = __ldg(&wrow[c]);
        u64 w2 = pk2(w, w);
        const u64* pr = (const u64*)&src_s[c * 22];
        #pragma unroll
        for (int t = 0; t < 10; t++) ffma2(acc[t], w2, pr[t]);
    }
    #pragma unroll
    for (int t = 0; t < 10; t++) {
        #pragma unroll
        for (int s = 8; s; s >>= 1)
            fadd2(acc[t], __shfl_xor_sync(0xffffffffu, acc[t], s));
    }
    if (g == 0) {
        float bi = bv[o], sc = sv[o], ta = tv[o];
        float* dp = dst + (size_t)(n * KC + o) * 20;
        #pragma unroll
        for (int t = 0; t < 10; t++) {
            float2 v = upk(acc[t]);
            dp[2 * t] = fmaxf((v.x + bi) * sc + ta, 0.f);
            if (2 * t + 1 < KCL) dp[2 * t + 1] = fmaxf((v.y + bi) * sc + ta, 0.f);
        }
    }
}

// ==================== Wv[n,o,k] = sum_c wu[o,c] * val[n,c,k] (raw) ====================
__global__ __launch_bounds__(256) void wv_gemm(const float* __restrict__ wu) {
    __shared__ float src_s[KC * 22];
    const int n = blockIdx.y;
    for (int idx = threadIdx.x; idx < KC * 20; idx += 256)
        src_s[(idx / 20) * 22 + (idx % 20)] = g_val[(size_t)n * KC * 20 + idx];
    __syncthreads();

    const int g  = threadIdx.x & 15;
    const int ol = threadIdx.x >> 4;
    const int o  = blockIdx.x * 16 + ol;     // grid.x = 32

    u64 acc[10];
    #pragma unroll
    for (int t = 0; t < 10; t++) acc[t] = 0ull;

    const float* wrow = wu + (size_t)o * KC;
    for (int cc = 0; cc < 16; cc++) {
        int c = g + cc * 16;
        float w = __ldg(&wrow[c]);
        u64 w2 = pk2(w, w);
        const u64* pr = (const u64*)&src_s[c * 22];
        #pragma unroll
        for (int t = 0; t < 10; t++) ffma2(acc[t], w2, pr[t]);
    }
    #pragma unroll
    for (int t = 0; t < 10; t++) {
        #pragma unroll
        for (int s = 8; s; s >>= 1)
            fadd2(acc[t], __shfl_xor_sync(0xffffffffu, acc[t], s));
    }
    if (g == 0) {
        float* dp = g_wv + (size_t)(n * OUTC + o) * 20;
        #pragma unroll
        for (int t = 0; t < 10; t++) {
            float2 v = upk(acc[t]);
            dp[2 * t] = v.x;
            if (2 * t + 1 < KCL) dp[2 * t + 1] = v.y;
        }
    }
}

// ==================== converters ====================
__global__ __launch_bounds__(256) void conv_feats2(const float* __restrict__ X) {
    const size_t TOT4 = (size_t)NB * CIN * HWD / 4;
    size_t i4 = (size_t)blockIdx.x * 256 + threadIdx.x;
    if (i4 >= TOT4) return;
    size_t row = i4 >> 12;
    int s = (int)(i4 & 4095) * 4;
    int n = (int)(row >> 9), c = (int)(row & 511);
    float4 v = *(const float4*)(X + row * HWD + s);
    __nv_bfloat16 h0, h1, h2, h3, l0, l1, l2, l3;
    split_bf16(v.x, h0, l0); split_bf16(v.y, h1, l1);
    split_bf16(v.z, h2, l2); split_bf16(v.w, h3, l3);
    __nv_bfloat16* hi = g_feats2 + ((size_t)n * 2 * CIN + c) * HWD + s;
    __nv_bfloat16* lo = hi + (size_t)CIN * HWD;
    *(u32*)hi = pack_bf2(h0, h1); *(u32*)(hi + 2) = pack_bf2(h2, h3);
    *(u32*)lo = pack_bf2(l0, l1); *(u32*)(lo + 2) = pack_bf2(l2, l3);
}

__global__ __launch_bounds__(256) void conv_w(const float* __restrict__ W,
                                              __nv_bfloat16* __restrict__ A2,
                                              int MK) {
    int i = blockIdx.x * 256 + threadIdx.x;
    if (i >= MK) return;
    __nv_bfloat16 h, l;
    split_bf16(W[i], h, l);
    A2[i] = h;
    A2[MK + i] = l;
}

// ==================== cp.async 2-stage compensated-bf16 GEMM + CBR ====================
#define A_PL 10240
#define B_PL 8704
#define ST_BYTES (2 * A_PL + 2 * B_PL)    // 37888
#define GEMM_SMEM (2 * ST_BYTES)          // 75776  (2 CTA/SM)

__global__ __launch_bounds__(256, 2) void gemm_cp2(
    const __nv_bfloat16* __restrict__ W2, int K, int nMB,
    const __nv_bfloat16* __restrict__ B0, long sB0, long pl0,
    const __nv_bfloat16* __restrict__ B1, long sB1, long pl1, int Ksplit,
    const float* __restrict__ bias, const float* __restrict__ scale,
    const float* __restrict__ tadd,
    float* __restrict__ Yf, long sYf,
    __nv_bfloat16* __restrict__ Y2, long sY2, long plY)
{
    extern __shared__ __align__(16) char smem[];
    const u32 sb = smem_u32(smem);

    const int n = blockIdx.z;
    const int m0 = (blockIdx.x % nMB) * BM;
    const int s0 = (blockIdx.x / nMB) * BN;

    const int tid = threadIdx.x;
    const int lane = tid & 31, warp = tid >> 5;
    const int wm = warp >> 2, wn = warp & 3;

    const __nv_bfloat16* b0h = B0 + (size_t)n * sB0;
    const __nv_bfloat16* b0l = b0h + pl0;
    const __nv_bfloat16* b1h = B1 + (size_t)n * sB1;
    const __nv_bfloat16* b1l = b1h + pl1;
    const size_t WloOff = (size_t)nMB * BM * K;

    float acc[4][4][4];
    #pragma unroll
    for (int mi = 0; mi < 4; mi++)
        #pragma unroll
        for (int ni = 0; ni < 4; ni++)
            #pragma unroll
            for (int q = 0; q < 4; q++) acc[mi][ni][q] = 0.f;

    const int nT = K / BK;

    const int idA0 = tid;
    const int idB0 = tid;

    auto load_stage = [&](int t, int buf) {
        const int kt = t * BK;
        const u32 st = sb + buf * ST_BYTES;
        #pragma unroll
        for (int i = 0; i < 4; i++) {
            int id = idA0 + i * 256;
            int plane = id >> 9, e = id & 511;
            int row = e >> 2, c = e & 3;
            const __nv_bfloat16* src = W2 + (plane ? WloOff : 0)
                + (size_t)(m0 + row) * K + kt + c * 8;
            cp16(st + (plane ? A_PL : 0) + row * 80 + c * 16, src);
        }
        #pragma unroll
        for (int i = 0; i < 4; i++) {
            int id = idB0 + i * 256;
            int plane = id >> 9, e = id & 511;
            int row = e >> 4, c = e & 15;
            int r = kt + row;
            const __nv_bfloat16* base = (r < Ksplit)
                ? (plane ? b0l : b0h) + (size_t)r * HWD
                : (plane ? b1l : b1h) + (size_t)(r - Ksplit) * HWD;
            cp16(st + 2 * A_PL + (plane ? B_PL : 0) + row * 272 + c * 16,
                 base + s0 + c * 8);
        }
    };

    const u32 aOff = ((wm * 64 + (lane & 15)) * 40 + ((lane >> 4) << 3)) * 2;
    const u32 bOff = ((lane & 15) * 136 + wn * 32 + ((lane >> 4) << 3)) * 2;
    const u32 A_MI = 16 * 40 * 2;
    const u32 B_KS = 16 * 136 * 2;

    load_stage(0, 0);
    CP_COMMIT();

    for (int t = 0; t < nT; t++) {
        CP_WAIT0();
        __syncthreads();
        if (t + 1 < nT) {
            load_stage(t + 1, (t + 1) & 1);
            CP_COMMIT();
        }

        const u32 st = sb + (t & 1) * ST_BYTES;
        const u32 ahA = st + aOff;
        const u32 alA = st + A_PL + aOff;
        const u32 bhA = st + 2 * A_PL + bOff;
        const u32 blA = st + 2 * A_PL + B_PL + bOff;

        #pragma unroll
        for (int ks = 0; ks < 2; ks++) {
            u32 rbh0[4], rbh1[4], rbl0[4], rbl1[4];
            ldsm4t(rbh0, bhA + ks * B_KS);
            ldsm4t(rbh1, bhA + ks * B_KS + 32);
            ldsm4t(rbl0, blA + ks * B_KS);
            ldsm4t(rbl1, blA + ks * B_KS + 32);

            u32 ra[4][4];
            #pragma unroll
            for (int mi = 0; mi < 4; mi++) ldsm4(ra[mi], ahA + mi * A_MI + ks * 32);
            #pragma unroll
            for (int mi = 0; mi < 4; mi++) {
                mma16816(acc[mi][0], ra[mi], &rbh0[0]);
                mma16816(acc[mi][1], ra[mi], &rbh0[2]);
                mma16816(acc[mi][2], ra[mi], &rbh1[0]);
                mma16816(acc[mi][3], ra[mi], &rbh1[2]);
            }
            #pragma unroll
            for (int mi = 0; mi < 4; mi++) {
                mma16816(acc[mi][0], ra[mi], &rbl0[0]);
                mma16816(acc[mi][1], ra[mi], &rbl0[2]);
                mma16816(acc[mi][2], ra[mi], &rbl1[0]);
                mma16816(acc[mi][3], ra[mi], &rbl1[2]);
            }
            #pragma unroll
            for (int mi = 0; mi < 4; mi++) ldsm4(ra[mi], alA + mi * A_MI + ks * 32);
            #pragma unroll
            for (int mi = 0; mi < 4; mi++) {
                mma16816(acc[mi][0], ra[mi], &rbh0[0]);
                mma16816(acc[mi][1], ra[mi], &rbh0[2]);
                mma16816(acc[mi][2], ra[mi], &rbh1[0]);
                mma16816(acc[mi][3], ra[mi], &rbh1[2]);
            }
        }
    }

    // ---- epilogue ----
    const int orow = lane >> 2;
    const int scol = (lane & 3) * 2;
    if (Yf) {
        float* y = Yf + (size_t)n * sYf;
        #pragma unroll
        for (int mi = 0; mi < 4; mi++) {
            const int oA = m0 + wm * 64 + mi * 16 + orow;
            const int oB = oA + 8;
            const float biA = bias[oA], scA = scale[oA], taA = tadd[oA];
            const float biB = bias[oB], scB = scale[oB], taB = tadd[oB];
            #pragma unroll
            for (int ni = 0; ni < 4; ni++) {
                const int s = s0 + wn * 32 + ni * 8 + scol;
                float2 r0 = make_float2(
                    fmaxf((acc[mi][ni][0] + biA) * scA + taA, 0.f),
                    fmaxf((acc[mi][ni][1] + biA) * scA + taA, 0.f));
                float2 r1 = make_float2(
                    fmaxf((acc[mi][ni][2] + biB) * scB + taB, 0.f),
                    fmaxf((acc[mi][ni][3] + biB) * scB + taB, 0.f));
                *(float2*)(y + (size_t)oA * HWD + s) = r0;
                *(float2*)(y + (size_t)oB * HWD + s) = r1;
            }
        }
    } else {
        __nv_bfloat16* yh = Y2 + (size_t)n * sY2;
        __nv_bfloat16* yl = yh + plY;
        #pragma unroll
        for (int mi = 0; mi < 4; mi++) {
            const int oA = m0 + wm * 64 + mi * 16 + orow;
            const int oB = oA + 8;
            const float biA = bias[oA], scA = scale[oA], taA = tadd[oA];
            const float biB = bias[oB], scB = scale[oB], taB = tadd[oB];
            #pragma unroll
            for (int ni = 0; ni < 4; ni++) {
                const int s = s0 + wn * 32 + ni * 8 + scol;
                float vA0 = fmaxf((acc[mi][ni][0] + biA) * scA + taA, 0.f);
                float vA1 = fmaxf((acc[mi][ni][1] + biA) * scA + taA, 0.f);
                float vB0 = fmaxf((acc[mi][ni][2] + biB) * scB + taB, 0.f);
                float vB1 = fmaxf((acc[mi][ni][3] + biB) * scB + taB, 0.f);
                __nv_bfloat16 hA0, lA0, hA1, lA1, hB0, lB0, hB1, lB1;
                split_bf16(vA0, hA0, lA0); split_bf16(vA1, hA1, lA1);
                split_bf16(vB0, hB0, lB0); split_bf16(vB1, hB1, lB1);
                *(u32*)(yh + (size_t)oA * HWD + s) = pack_bf2(hA0, hA1);
                *(u32*)(yl + (size_t)oA * HWD + s) = pack_bf2(lA0, lA1);
                *(u32*)(yh + (size_t)oB * HWD + s) = pack_bf2(hB0, hB1);
                *(u32*)(yl + (size_t)oB * HWD + s) = pack_bf2(lB0, lB1);
            }
        }
    }
}

// ==================== attention + folded f_up (merged, 2 positions/thread) ====================
// block: 256 threads, positions [bx*512, bx*512+512), thread handles s0=bx*512+2*tid, s0+1.
// smem: kk (256x20 f32), wv (512x20 f32), prm (3x512) -> 66.5 KB dynamic.
#define ATTN_SMEM ((KC * 20 + OUTC * 20 + 3 * OUTC) * 4)

__global__ __launch_bounds__(256) void attn_up2_k(
    const float* __restrict__ bu, const float* __restrict__ su,
    const float* __restrict__ tu)
{
    extern __shared__ __align__(8) float dsm[];
    float* kk_s = dsm;                 // KC*20
    float* wv_s = kk_s + KC * 20;      // OUTC*20
    float* prm  = wv_s + OUTC * 20;    // 3*OUTC

    const int n = blockIdx.y;
    const int tid = threadIdx.x;

    for (int idx = tid; idx < KC * 20; idx += 256)
        kk_s[idx] = g_kk[(size_t)n * KC * 20 + idx];
    for (int idx = tid; idx < OUTC * 20; idx += 256)
        wv_s[idx] = g_wv[(size_t)n * OUTC * 20 + idx];
    for (int idx = tid; idx < OUTC; idx += 256) {
        prm[idx] = bu[idx];
        prm[OUTC + idx] = su[idx];
        prm[2 * OUTC + idx] = tu[idx];
    }
    __syncthreads();

    const int sa = blockIdx.x * 512 + tid * 2;    // handles sa, sa+1
    const float* qn = g_q2 + (size_t)n * KC * HWD;

    u64 lgA[10], lgB[10];
    #pragma unroll
    for (int t = 0; t < 10; t++) { lgA[t] = 0ull; lgB[t] = 0ull; }

    #pragma unroll 4
    for (int c = 0; c < KC; c++) {
        float2 q = *(const float2*)(qn + (size_t)c * HWD + sa);
        u64 qa2 = pk2(q.x, q.x), qb2 = pk2(q.y, q.y);
        const u64* kr = (const u64*)&kk_s[c * 20];
        #pragma unroll
        for (int t = 0; t < 10; t++) {
            u64 kv = kr[t];
            ffma2(lgA[t], qa2, kv);
            ffma2(lgB[t], qb2, kv);
        }
    }

    float la[20], lb[20];
    #pragma unroll
    for (int t = 0; t < 10; t++) {
        float2 va = upk(lgA[t]); la[2 * t] = va.x; la[2 * t + 1] = va.y;
        float2 vb = upk(lgB[t]); lb[2 * t] = vb.x; lb[2 * t + 1] = vb.y;
    }
    const float scl = 0.0625f;
    float mA = -3.4e38f, mB = -3.4e38f;
    #pragma unroll
    for (int k = 0; k < KCL; k++) {
        la[k] *= scl; lb[k] *= scl;
        mA = fmaxf(mA, la[k]); mB = fmaxf(mB, lb[k]);
    }
    float sA = 0.f, sB = 0.f;
    #pragma unroll
    for (int k = 0; k < KCL; k++) {
        la[k] = __expf(la[k] - mA); sA += la[k];
        lb[k] = __expf(lb[k] - mB); sB += lb[k];
    }
    const float ivA = 1.f / sA, ivB = 1.f / sB;
    #pragma unroll
    for (int k = 0; k < KCL; k++) { la[k] *= ivA; lb[k] *= ivB; }
    la[19] = 0.f; lb[19] = 0.f;

    u64 sA2[10], sB2[10];
    #pragma unroll
    for (int t = 0; t < 10; t++) {
        sA2[t] = pk2(la[2 * t], la[2 * t + 1]);
        sB2[t] = pk2(lb[2 * t], lb[2 * t + 1]);
    }

    __nv_bfloat16* uph = g_up2 + (size_t)n * 2 * CIN * HWD + sa;
    __nv_bfloat16* upl = uph + (size_t)CIN * HWD;

    #pragma unroll 4
    for (int oo = 0; oo < OUTC; oo++) {
        const u64* vr = (const u64*)&wv_s[oo * 20];
        u64 aA = 0ull, aB = 0ull;
        #pragma unroll
        for (int t = 0; t < 10; t++) {
            u64 vv = vr[t];
            ffma2(aA, sA2[t], vv);
            ffma2(aB, sB2[t], vv);
        }
        float2 va = upk(aA), vb = upk(aB);
        const float bi = prm[oo], sc = prm[OUTC + oo], ta = prm[2 * OUTC + oo];
        float f0 = fmaxf(((va.x + va.y) + bi) * sc + ta, 0.f);
        float f1 = fmaxf(((vb.x + vb.y) + bi) * sc + ta, 0.f);
        __nv_bfloat16 h0, l0, h1, l1;
        split_bf16(f0, h0, l0);
        split_bf16(f1, h1, l1);
        *(u32*)(uph + (size_t)oo * HWD) = pack_bf2(h0, h1);
        *(u32*)(upl + (size_t)oo * HWD) = pack_bf2(l0, l1);
    }
}

// ==================== host driver ====================
extern "C" void kernel_launch(void* const* d_in, const int* in_sizes, int n_in,
                              void* d_out, int out_size) {
    const float* feats = (const float*)d_in[0];
    const float* probs = (const float*)d_in[1];
    const float* wp1 = (const float*)d_in[2];
    const float* bp1 = (const float*)d_in[3];
    const float* sp1 = (const float*)d_in[4];
    const float* tp1 = (const float*)d_in[5];
    const float* wp2 = (const float*)d_in[6];
    const float* bp2 = (const float*)d_in[7];
    const float* sp2 = (const float*)d_in[8];
    const float* tp2 = (const float*)d_in[9];
    const float* wo1 = (const float*)d_in[10];
    const float* bo1 = (const float*)d_in[11];
    const float* so1 = (const float*)d_in[12];
    const float* to1 = (const float*)d_in[13];
    const float* wo2 = (const float*)d_in[14];
    const float* bo2 = (const float*)d_in[15];
    const float* so2 = (const float*)d_in[16];
    const float* to2 = (const float*)d_in[17];
    const float* wd  = (const float*)d_in[18];
    const float* bd  = (const float*)d_in[19];
    const float* sd  = (const float*)d_in[20];
    const float* td  = (const float*)d_in[21];
    const float* wu  = (const float*)d_in[22];
    const float* bu  = (const float*)d_in[23];
    const float* su  = (const float*)d_in[24];
    const float* tu  = (const float*)d_in[25];
    const float* wf  = (const float*)d_in[26];
    const float* bf  = (const float*)d_in[27];
    const float* sf  = (const float*)d_in[28];
    const float* tf  = (const float*)d_in[29];
    float* out = (float*)d_out;

    void *pproxy, *pt1, *pkk, *pval, *pq2, *pf2, *pq12, *pup2;
    void *pw1, *pw2, *pwf;
    cudaGetSymbolAddress(&pproxy, g_proxy);
    cudaGetSymbolAddress(&pt1, g_t1);
    cudaGetSymbolAddress(&pkk, g_kk);
    cudaGetSymbolAddress(&pval, g_val);
    cudaGetSymbolAddress(&pq2, g_q2);
    cudaGetSymbolAddress(&pf2, g_feats2);
    cudaGetSymbolAddress(&pq12, g_q12);
    cudaGetSymbolAddress(&pup2, g_up2);
    cudaGetSymbolAddress(&pw1, g_wp1_2);
    cudaGetSymbolAddress(&pw2, g_wp2_2);
    cudaGetSymbolAddress(&pwf, g_wf_2);

    cudaFuncSetAttribute(gemm_cp2, cudaFuncAttributeMaxDynamicSharedMemorySize, GEMM_SMEM);
    cudaFuncSetAttribute(attn_up2_k, cudaFuncAttributeMaxDynamicSharedMemorySize, ATTN_SMEM);

    // converters
    conv_feats2<<<(NB * CIN * HWD / 4 + 255) / 256, 256>>>(feats);
    conv_w<<<(KC * CIN + 255) / 256, 256>>>(wp1, (__nv_bfloat16*)pw1, KC * CIN);
    conv_w<<<(KC * KC + 255) / 256, 256>>>(wp2, (__nv_bfloat16*)pw2, KC * KC);
    conv_w<<<(OUTC * 2 * CIN + 255) / 256, 256>>>(wf, (__nv_bfloat16*)pwf, OUTC * 2 * CIN);

    // softmax + proxy + object branch + Wv
    softmax_k<<<NB * KCL, 256>>>(probs);
    proxy_k<<<dim3(32, NB), 256>>>(feats);
    obj_gemm<<<dim3(16, NB), 256, CIN * 22 * 4>>>(wo1, bo1, so1, to1,
        (const float*)pproxy, (float*)pt1, CIN);
    obj_gemm<<<dim3(16, NB), 256, CIN * 22 * 4>>>(wd, bd, sd, td,
        (const float*)pproxy, (float*)pval, CIN);
    obj_gemm<<<dim3(16, NB), 256, KC * 22 * 4>>>(wo2, bo2, so2, to2,
        (const float*)pt1, (float*)pkk, KC);
    wv_gemm<<<dim3(32, NB), 256>>>(wu);

    // q1 = cbr(wp1 @ feats) -> planes            M=256, K=512
    gemm_cp2<<<dim3((HWD / BN) * (KC / BM), 1, NB), 256, GEMM_SMEM>>>(
        (const __nv_bfloat16*)pw1, CIN, KC / BM,
        (const __nv_bfloat16*)pf2, 2L * CIN * HWD, (long)CIN * HWD,
        (const __nv_bfloat16*)pf2, 2L * CIN * HWD, (long)CIN * HWD, CIN,
        bp1, sp1, tp1,
        nullptr, 0,
        (__nv_bfloat16*)pq12, 2L * KC * HWD, (long)KC * HWD);

    // q2 = cbr(wp2 @ q1) -> fp32                 M=256, K=256
    gemm_cp2<<<dim3((HWD / BN) * (KC / BM), 1, NB), 256, GEMM_SMEM>>>(
        (const __nv_bfloat16*)pw2, KC, KC / BM,
        (const __nv_bfloat16*)pq12, 2L * KC * HWD, (long)KC * HWD,
        (const __nv_bfloat16*)pq12, 2L * KC * HWD, (long)KC * HWD, KC,
        bp2, sp2, tp2,
        (float*)pq2, (long)KC * HWD,
        nullptr, 0, 0);

    // attention + folded f_up -> up planes (merged, 2 pos/thread)
    attn_up2_k<<<dim3(HWD / 512, NB), 256, ATTN_SMEM>>>(bu, su, tu);

    // out = cbr(wf @ cat[up, feats]) -> fp32     M=512, K=1024, Ksplit=512
    gemm_cp2<<<dim3((HWD / BN) * (OUTC / BM), 1, NB), 256, GEMM_SMEM>>>(
        (const __nv_bfloat16*)pwf, 2 * CIN, OUTC / BM,
        (const __nv_bfloat16*)pup2, 2L * CIN * HWD, (long)CIN * HWD,
        (const __nv_bfloat16*)pf2, 2L * CIN * HWD, (long)CIN * HWD, CIN,
        bf, sf, tf,
        out, (long)OUTC * HWD,
        nullptr, 0, 0);
}